// round 1
// baseline (speedup 1.0000x reference)
#include <cuda_runtime.h>

// Single scalar accumulator in device global memory (no allocations allowed).
__device__ double g_acc;

__global__ void zero_acc_kernel() {
    if (threadIdx.x == 0 && blockIdx.x == 0) g_acc = 0.0;
}

// Per-row work: CE term (log-sum-exp - picked logit), and r2 statistics
// (squared deviation of alt_p from 0.5, het count).
__device__ __forceinline__ float row_loss(float l0, float l1, float l2, int t,
                                          float& ssq, int& nhet) {
    float m  = fmaxf(l0, fmaxf(l1, l2));
    float e0 = __expf(l0 - m);
    float e1 = __expf(l1 - m);
    float e2 = __expf(l2 - m);
    float s  = e0 + e1 + e2;
    // picked logit (targets are always in {0,1,2} for this problem)
    float lt = (t == 1) ? l1 : ((t == 2) ? l2 : l0);
    float ce = __logf(s) + m - lt;          // -log_softmax[target]
    float p0 = __fdividef(e0, s);           // probs[:,0]
    float d  = 0.5f - p0;                   // alt_p - af2 = (1-p0) - 0.5
    ssq  += d * d;
    nhet += (t == 1);
    return ce;
}

__global__ void imputation_loss_kernel(const float4* __restrict__ lg,
                                       const int4*  __restrict__ tg,
                                       long long ngroups,
                                       const float* __restrict__ logits_tail,
                                       const int*   __restrict__ targets_tail,
                                       int tail_rows) {
    double local = 0.0;
    const long long stride = (long long)gridDim.x * blockDim.x;
    for (long long g = blockIdx.x * (long long)blockDim.x + threadIdx.x;
         g < ngroups; g += stride) {
        // 4 rows x 3 logits = 12 floats = 3 float4 (contiguous 48B per thread)
        float4 a = lg[g * 3 + 0];
        float4 b = lg[g * 3 + 1];
        float4 c = lg[g * 3 + 2];
        int4   t = tg[g];
        float ce = 0.0f, ssq = 0.0f;
        int nhet = 0;
        ce += row_loss(a.x, a.y, a.z, t.x, ssq, nhet);
        ce += row_loss(a.w, b.x, b.y, t.y, ssq, nhet);
        ce += row_loss(b.z, b.w, c.x, t.z, ssq, nhet);
        ce += row_loss(c.y, c.z, c.w, t.w, ssq, nhet);
        // group r2 contribution: -(nhet) * (ssq/cnt)/0.25 * cnt = -4*nhet*ssq
        local += (double)(ce - 4.0f * (float)nhet * ssq);
    }

    // Tail group (rows beyond ngroups*4), handled by a single thread.
    // Same -4*nhet*ssq formula (cnt cancels out of the group term).
    if (blockIdx.x == 0 && threadIdx.x == 0 && tail_rows > 0) {
        float ce = 0.0f, ssq = 0.0f;
        int nhet = 0;
        for (int r = 0; r < tail_rows; r++) {
            float l0 = logits_tail[r * 3 + 0];
            float l1 = logits_tail[r * 3 + 1];
            float l2 = logits_tail[r * 3 + 2];
            ce += row_loss(l0, l1, l2, targets_tail[r], ssq, nhet);
        }
        local += (double)(ce - 4.0f * (float)nhet * ssq);
    }

    // Warp reduce (double)
    #pragma unroll
    for (int o = 16; o > 0; o >>= 1)
        local += __shfl_down_sync(0xffffffffu, local, o);

    __shared__ double ws[8];
    if ((threadIdx.x & 31) == 0) ws[threadIdx.x >> 5] = local;
    __syncthreads();
    if (threadIdx.x < 8) {
        double v = ws[threadIdx.x];
        #pragma unroll
        for (int o = 4; o > 0; o >>= 1)
            v += __shfl_down_sync(0xffu, v, o);
        if (threadIdx.x == 0) atomicAdd(&g_acc, v);
    }
}

__global__ void finalize_kernel(float* out) {
    if (threadIdx.x == 0 && blockIdx.x == 0) out[0] = (float)g_acc;
}

extern "C" void kernel_launch(void* const* d_in, const int* in_sizes, int n_in,
                              void* d_out, int out_size) {
    const float* logits  = (const float*)d_in[0];   // (N, 3) fp32
    const int*   targets = (const int*)d_in[1];     // (N,)  int32
    float* out = (float*)d_out;

    const long long n       = in_sizes[1];          // number of rows
    const long long ngroups = n / 4;
    const int tail_rows     = (int)(n - ngroups * 4);

    const int threads = 256;
    const int blocks  = 1184;  // 148 SMs * 8 blocks -> 64 warps/SM resident

    zero_acc_kernel<<<1, 32>>>();
    imputation_loss_kernel<<<blocks, threads>>>(
        (const float4*)logits, (const int4*)targets, ngroups,
        logits + ngroups * 4 * 3, targets + ngroups * 4, tail_rows);
    finalize_kernel<<<1, 32>>>(out);
}

// round 2
// speedup vs baseline: 1.0696x; 1.0696x over previous
#include <cuda_runtime.h>

// Scalar accumulator + completion counter in device globals (no allocs allowed).
// Both are self-resetting: the last block restores them to their initial state,
// so the kernel is deterministic across CUDA-graph replays.
__device__ double       g_acc  = 0.0;
__device__ unsigned int g_done = 0u;

// Per-row work: CE term (log-sum-exp - picked logit), and r2 statistics
// (squared deviation of alt_p from 0.5, het count).
__device__ __forceinline__ float row_loss(float l0, float l1, float l2, int t,
                                          float& ssq, int& nhet) {
    float m  = fmaxf(l0, fmaxf(l1, l2));
    float e0 = __expf(l0 - m);
    float e1 = __expf(l1 - m);
    float e2 = __expf(l2 - m);
    float s  = e0 + e1 + e2;
    float lt = (t == 1) ? l1 : ((t == 2) ? l2 : l0);
    float ce = __logf(s) + m - lt;          // -log_softmax[target]
    float p0 = __fdividef(e0, s);           // probs[:,0]
    float d  = 0.5f - p0;                   // alt_p - af2 = (1-p0) - 0.5
    ssq  += d * d;
    nhet += (t == 1);
    return ce;
}

__global__ void imputation_loss_kernel(const float4* __restrict__ lg,
                                       const int4*  __restrict__ tg,
                                       int ngroups,
                                       const float* __restrict__ logits_tail,
                                       const int*   __restrict__ targets_tail,
                                       int tail_rows,
                                       float* __restrict__ out) {
    double local = 0.0;
    const int stride = gridDim.x * blockDim.x;
    for (int g = blockIdx.x * blockDim.x + threadIdx.x; g < ngroups; g += stride) {
        // 4 rows x 3 logits = 12 floats = 3 float4 (contiguous 48B per thread)
        float4 a = lg[g * 3 + 0];
        float4 b = lg[g * 3 + 1];
        float4 c = lg[g * 3 + 2];
        int4   t = tg[g];
        float ce = 0.0f, ssq = 0.0f;
        int nhet = 0;
        ce += row_loss(a.x, a.y, a.z, t.x, ssq, nhet);
        ce += row_loss(a.w, b.x, b.y, t.y, ssq, nhet);
        ce += row_loss(b.z, b.w, c.x, t.z, ssq, nhet);
        ce += row_loss(c.y, c.z, c.w, t.w, ssq, nhet);
        // group r2 contribution: -(nhet) * (ssq/cnt)/0.25 * cnt = -4*nhet*ssq
        local += (double)(ce - 4.0f * (float)nhet * ssq);
    }

    // Tail group (rows beyond ngroups*4). Same -4*nhet*ssq formula
    // (cnt cancels out of the group term), handled by one thread.
    if (blockIdx.x == 0 && threadIdx.x == 0 && tail_rows > 0) {
        float ce = 0.0f, ssq = 0.0f;
        int nhet = 0;
        for (int r = 0; r < tail_rows; r++) {
            ce += row_loss(logits_tail[r * 3 + 0], logits_tail[r * 3 + 1],
                           logits_tail[r * 3 + 2], targets_tail[r], ssq, nhet);
        }
        local += (double)(ce - 4.0f * (float)nhet * ssq);
    }

    // Warp reduce (double)
    #pragma unroll
    for (int o = 16; o > 0; o >>= 1)
        local += __shfl_down_sync(0xffffffffu, local, o);

    __shared__ double ws[8];
    if ((threadIdx.x & 31) == 0) ws[threadIdx.x >> 5] = local;
    __syncthreads();

    if (threadIdx.x == 0) {
        double v = 0.0;
        #pragma unroll
        for (int w = 0; w < 8; w++) v += ws[w];

        atomicAdd(&g_acc, v);
        __threadfence();
        unsigned int ticket = atomicAdd(&g_done, 1u);
        if (ticket == gridDim.x - 1) {
            // Last block: every other block's atomicAdd happened-before its
            // counter bump, so the sum is complete and visible.
            double total = atomicAdd(&g_acc, 0.0);   // coherent L2 read
            out[0] = (float)total;
            g_acc  = 0.0;   // self-reset for the next graph replay
            __threadfence();
            g_done = 0u;
        }
    }
}

extern "C" void kernel_launch(void* const* d_in, const int* in_sizes, int n_in,
                              void* d_out, int out_size) {
    const float* logits  = (const float*)d_in[0];   // (N, 3) fp32
    const int*   targets = (const int*)d_in[1];     // (N,)  int32
    float* out = (float*)d_out;

    const int n       = in_sizes[1];                // number of rows
    const int ngroups = n / 4;
    const int tail_rows = n - ngroups * 4;

    const int threads = 256;
    const int blocks  = 1184;  // 148 SMs * 8 blocks -> 64 warps/SM resident

    imputation_loss_kernel<<<blocks, threads>>>(
        (const float4*)logits, (const int4*)targets, ngroups,
        logits + (long long)ngroups * 12, targets + (long long)ngroups * 4,
        tail_rows, out);
}